// round 1
// baseline (speedup 1.0000x reference)
#include <cuda_runtime.h>
#include <cuda_fp16.h>
#include <cstdint>

#define M_DIM 8192
#define N_DIM 4096
#define K_DIM 4096

#define BM 128
#define BN 128
#define BK 32

// Scratch: hi/lo fp16 split of quant-dequantized x and w (exact to ~2^-22 rel).
__device__ __half g_xh[(size_t)M_DIM * K_DIM];
__device__ __half g_xl[(size_t)M_DIM * K_DIM];
__device__ __half g_wh[(size_t)N_DIM * K_DIM];
__device__ __half g_wl[(size_t)N_DIM * K_DIM];

// ---------------------------------------------------------------------------
// Quant + split kernel: each quad (4 threads) owns one 16-element NVFP4 block.
// Matches reference exactly: scale = amax/6 (fp32 divide), round-half-even.
// ---------------------------------------------------------------------------
__global__ void quant_split_kernel(const float* __restrict__ src, int is_w, int nquads)
{
    int t = blockIdx.x * blockDim.x + threadIdx.x;
    int quad = t >> 2;
    int lq = t & 3;
    if (quad >= nquads) return;

    __half* __restrict__ H = is_w ? g_wh : g_xh;
    __half* __restrict__ L = is_w ? g_wl : g_xl;

    size_t base = (size_t)quad * 16 + (size_t)lq * 4;
    float4 v = *reinterpret_cast<const float4*>(src + base);

    float amax = fmaxf(fmaxf(fabsf(v.x), fabsf(v.y)), fmaxf(fabsf(v.z), fabsf(v.w)));
    amax = fmaxf(amax, __shfl_xor_sync(0xffffffffu, amax, 1));
    amax = fmaxf(amax, __shfl_xor_sync(0xffffffffu, amax, 2));

    float scale = (amax > 0.0f) ? (amax / 6.0f) : 1.0f;

    float vals[4] = {v.x, v.y, v.z, v.w};
    unsigned short hs[4], ls[4];
#pragma unroll
    for (int i = 0; i < 4; i++) {
        float y = vals[i] / scale;
        float a = fabsf(y);
        a = fminf(a, 6.0f);
        if (a <= 2.0f)       a = rintf(a * 2.0f) * 0.5f;   // step 0.5 region
        else if (a <= 4.0f)  a = rintf(a);                 // step 1.0 region
        else                 a = rintf(a * 0.5f) * 2.0f;   // step 2.0 region
        float q  = copysignf(a, y);
        float xq = q * scale;                              // fp32 dequant value
        __half h = __float2half_rn(xq);
        float  lf = xq - __half2float(h);
        __half l = __float2half_rn(lf);
        hs[i] = __half_as_ushort(h);
        ls[i] = __half_as_ushort(l);
    }
    // 8-byte vector stores
    uint2 hp, lp;
    hp.x = (unsigned)hs[0] | ((unsigned)hs[1] << 16);
    hp.y = (unsigned)hs[2] | ((unsigned)hs[3] << 16);
    lp.x = (unsigned)ls[0] | ((unsigned)ls[1] << 16);
    lp.y = (unsigned)ls[2] | ((unsigned)ls[3] << 16);
    *reinterpret_cast<uint2*>(H + base) = hp;
    *reinterpret_cast<uint2*>(L + base) = lp;
}

// ---------------------------------------------------------------------------
// GEMM: C = Hx*Hw^T + Hx*Lw^T + Lx*Hw^T  (+ bias), fp16 inputs, fp32 accum.
// 128x128 CTA tile, BK=32, 8 warps (2x4), warp tile 64x32, mma.m16n8k16.
// Double-buffered cp.async, XOR-swizzled smem (conflict-free ldmatrix).
// ---------------------------------------------------------------------------
__device__ __forceinline__ unsigned sptr(const void* p)
{
    return (unsigned)__cvta_generic_to_shared(p);
}

__global__ __launch_bounds__(256, 2)
void gemm3_kernel(const float* __restrict__ bias, float* __restrict__ out)
{
    __shared__ __half sA[2][BM * BK];
    __shared__ __half sB[2][BN * BK];

    const __half* Aseg[3] = {g_xh, g_xh, g_xl};
    const __half* Bseg[3] = {g_wh, g_wl, g_wh};

    const int tid  = threadIdx.x;
    const int warp = tid >> 5;
    const int lane = tid & 31;
    const int wm = warp >> 2;   // 0..1
    const int wn = warp & 3;    // 0..3
    const int mBase = blockIdx.y * BM;
    const int nBase = blockIdx.x * BN;

    float c[4][4][4];
#pragma unroll
    for (int i = 0; i < 4; i++)
#pragma unroll
        for (int j = 0; j < 4; j++)
#pragma unroll
            for (int r = 0; r < 4; r++) c[i][j][r] = 0.0f;

    const int KITERS = K_DIM / BK;      // 128
    const int NITER  = 3 * KITERS;      // 384

    auto load_tile = [&](int it, int buf) {
        int seg = it / KITERS;
        int kk  = (it % KITERS) * BK;
        const __half* A = Aseg[seg];
        const __half* B = Bseg[seg];
#pragma unroll
        for (int h = 0; h < 2; h++) {
            int q  = tid + h * 256;
            int r  = q >> 2;                 // row in tile (0..127)
            int cc = q & 3;                  // 16B chunk (0..3)
            int sw = r * BK + (((cc) ^ ((r >> 1) & 3)) << 3);
            const __half* gA = A + (size_t)(mBase + r) * K_DIM + kk + (cc << 3);
            unsigned dA = sptr(&sA[buf][sw]);
            asm volatile("cp.async.cg.shared.global [%0], [%1], 16;\n" :: "r"(dA), "l"(gA));
            const __half* gB = B + (size_t)(nBase + r) * K_DIM + kk + (cc << 3);
            unsigned dB = sptr(&sB[buf][sw]);
            asm volatile("cp.async.cg.shared.global [%0], [%1], 16;\n" :: "r"(dB), "l"(gB));
        }
        asm volatile("cp.async.commit_group;\n");
    };

    load_tile(0, 0);

    for (int it = 0; it < NITER; it++) {
        int buf = it & 1;
        if (it + 1 < NITER) {
            load_tile(it + 1, buf ^ 1);
            asm volatile("cp.async.wait_group 1;\n");
        } else {
            asm volatile("cp.async.wait_group 0;\n");
        }
        __syncthreads();

#pragma unroll
        for (int ks = 0; ks < 2; ks++) {    // two k16 steps per BK=32
            // A fragments: 4 x m16, ldmatrix.x4 each
            unsigned af[4][4];
#pragma unroll
            for (int mi = 0; mi < 4; mi++) {
                int mat = lane >> 3;
                int r   = wm * 64 + mi * 16 + ((mat & 1) << 3) + (lane & 7);
                int cc  = ks * 2 + (mat >> 1);
                int sw  = r * BK + (((cc) ^ ((r >> 1) & 3)) << 3);
                unsigned addr = sptr(&sA[buf][sw]);
                asm volatile(
                    "ldmatrix.sync.aligned.m8n8.x4.shared.b16 {%0,%1,%2,%3}, [%4];\n"
                    : "=r"(af[mi][0]), "=r"(af[mi][1]), "=r"(af[mi][2]), "=r"(af[mi][3])
                    : "r"(addr));
            }
            // B fragments: 4 x n8 (two ldmatrix.x4, each yields 2 frags)
            unsigned bf[4][2];
#pragma unroll
            for (int p = 0; p < 2; p++) {
                int mat = lane >> 3;
                int r   = wn * 32 + p * 16 + ((mat >> 1) << 3) + (lane & 7);
                int cc  = ks * 2 + (mat & 1);
                int sw  = r * BK + (((cc) ^ ((r >> 1) & 3)) << 3);
                unsigned addr = sptr(&sB[buf][sw]);
                unsigned r0, r1, r2, r3;
                asm volatile(
                    "ldmatrix.sync.aligned.m8n8.x4.shared.b16 {%0,%1,%2,%3}, [%4];\n"
                    : "=r"(r0), "=r"(r1), "=r"(r2), "=r"(r3)
                    : "r"(addr));
                bf[p * 2][0]     = r0;  // (n0-7, k0-7)
                bf[p * 2][1]     = r1;  // (n0-7, k8-15)
                bf[p * 2 + 1][0] = r2;  // (n8-15, k0-7)
                bf[p * 2 + 1][1] = r3;  // (n8-15, k8-15)
            }
#pragma unroll
            for (int mi = 0; mi < 4; mi++)
#pragma unroll
                for (int ni = 0; ni < 4; ni++) {
                    asm volatile(
                        "mma.sync.aligned.m16n8k16.row.col.f32.f16.f16.f32 "
                        "{%0,%1,%2,%3}, {%4,%5,%6,%7}, {%8,%9}, {%0,%1,%2,%3};\n"
                        : "+f"(c[mi][ni][0]), "+f"(c[mi][ni][1]),
                          "+f"(c[mi][ni][2]), "+f"(c[mi][ni][3])
                        : "r"(af[mi][0]), "r"(af[mi][1]), "r"(af[mi][2]), "r"(af[mi][3]),
                          "r"(bf[ni][0]), "r"(bf[ni][1]));
                }
        }
        __syncthreads();   // protect buf before it is refilled next iteration
    }

    // Epilogue: bias add + fp32 store
#pragma unroll
    for (int mi = 0; mi < 4; mi++) {
        int row0 = mBase + wm * 64 + mi * 16 + (lane >> 2);
#pragma unroll
        for (int ni = 0; ni < 4; ni++) {
            int col = nBase + wn * 32 + ni * 8 + ((lane & 3) << 1);
            float b0 = __ldg(bias + col);
            float b1 = __ldg(bias + col + 1);
            out[(size_t)row0 * N_DIM + col]           = c[mi][ni][0] + b0;
            out[(size_t)row0 * N_DIM + col + 1]       = c[mi][ni][1] + b1;
            out[(size_t)(row0 + 8) * N_DIM + col]     = c[mi][ni][2] + b0;
            out[(size_t)(row0 + 8) * N_DIM + col + 1] = c[mi][ni][3] + b1;
        }
    }
}

// ---------------------------------------------------------------------------
extern "C" void kernel_launch(void* const* d_in, const int* in_sizes, int n_in,
                              void* d_out, int out_size)
{
    const float* x    = (const float*)d_in[0];
    const float* w    = (const float*)d_in[1];
    const float* bias = (const float*)d_in[2];
    float* out        = (float*)d_out;

    const int xquads = M_DIM * K_DIM / 16;
    const int wquads = N_DIM * K_DIM / 16;

    quant_split_kernel<<<(xquads * 4 + 255) / 256, 256>>>(x, 0, xquads);
    quant_split_kernel<<<(wquads * 4 + 255) / 256, 256>>>(w, 1, wquads);

    dim3 grid(N_DIM / BN, M_DIM / BM);
    gemm3_kernel<<<grid, 256>>>(bias, out);
}

// round 2
// speedup vs baseline: 2.5539x; 2.5539x over previous
#include <cuda_runtime.h>
#include <cuda_fp16.h>
#include <cstdint>

#define M_DIM 8192
#define N_DIM 4096
#define K_DIM 4096

#define BM 128
#define BN 128
#define BK 32

// Scratch: fp16 quant-dequantized x and w.
__device__ __half g_xh[(size_t)M_DIM * K_DIM];
__device__ __half g_wh[(size_t)N_DIM * K_DIM];

// ---------------------------------------------------------------------------
// Quant kernel: each quad (4 threads) owns one 16-element NVFP4 block.
// Matches reference: scale = amax/6 (fp32 divide), round-half-even, then
// the dequantized value rounded once to fp16 (adds ~1.4e-4 RMS rel noise,
// well under the fp32-accumulation floor of the reference comparison).
// ---------------------------------------------------------------------------
__global__ void quant_kernel(const float* __restrict__ src, int is_w, int nquads)
{
    int t = blockIdx.x * blockDim.x + threadIdx.x;
    int quad = t >> 2;
    int lq = t & 3;
    if (quad >= nquads) return;

    __half* __restrict__ H = is_w ? g_wh : g_xh;

    size_t base = (size_t)quad * 16 + (size_t)lq * 4;
    float4 v = *reinterpret_cast<const float4*>(src + base);

    float amax = fmaxf(fmaxf(fabsf(v.x), fabsf(v.y)), fmaxf(fabsf(v.z), fabsf(v.w)));
    amax = fmaxf(amax, __shfl_xor_sync(0xffffffffu, amax, 1));
    amax = fmaxf(amax, __shfl_xor_sync(0xffffffffu, amax, 2));

    float scale = (amax > 0.0f) ? (amax / 6.0f) : 1.0f;

    float vals[4] = {v.x, v.y, v.z, v.w};
    unsigned short hs[4];
#pragma unroll
    for (int i = 0; i < 4; i++) {
        float y = vals[i] / scale;
        float a = fabsf(y);
        a = fminf(a, 6.0f);
        if (a <= 2.0f)       a = rintf(a * 2.0f) * 0.5f;   // step 0.5 region
        else if (a <= 4.0f)  a = rintf(a);                 // step 1.0 region
        else                 a = rintf(a * 0.5f) * 2.0f;   // step 2.0 region
        float q  = copysignf(a, y);
        float xq = q * scale;                              // fp32 dequant value
        hs[i] = __half_as_ushort(__float2half_rn(xq));
    }
    uint2 hp;
    hp.x = (unsigned)hs[0] | ((unsigned)hs[1] << 16);
    hp.y = (unsigned)hs[2] | ((unsigned)hs[3] << 16);
    *reinterpret_cast<uint2*>(H + base) = hp;
}

// ---------------------------------------------------------------------------
// GEMM: C = Xq * Wq^T (+ bias), fp16 inputs, fp32 accum.
// 128x128 CTA tile, BK=32, 8 warps (2x4), warp tile 64x32, mma.m16n8k16.
// Double-buffered cp.async, XOR-swizzled smem (conflict-free ldmatrix).
// ---------------------------------------------------------------------------
__device__ __forceinline__ unsigned sptr(const void* p)
{
    return (unsigned)__cvta_generic_to_shared(p);
}

__global__ __launch_bounds__(256, 2)
void gemm_kernel(const float* __restrict__ bias, float* __restrict__ out)
{
    __shared__ __half sA[2][BM * BK];
    __shared__ __half sB[2][BN * BK];

    const int tid  = threadIdx.x;
    const int warp = tid >> 5;
    const int lane = tid & 31;
    const int wm = warp >> 2;   // 0..1
    const int wn = warp & 3;    // 0..3
    const int mBase = blockIdx.y * BM;
    const int nBase = blockIdx.x * BN;

    float c[4][4][4];
#pragma unroll
    for (int i = 0; i < 4; i++)
#pragma unroll
        for (int j = 0; j < 4; j++)
#pragma unroll
            for (int r = 0; r < 4; r++) c[i][j][r] = 0.0f;

    const int NITER = K_DIM / BK;      // 128

    auto load_tile = [&](int it, int buf) {
        int kk = it * BK;
#pragma unroll
        for (int h = 0; h < 2; h++) {
            int q  = tid + h * 256;
            int r  = q >> 2;                 // row in tile (0..127)
            int cc = q & 3;                  // 16B chunk (0..3)
            int sw = r * BK + (((cc) ^ ((r >> 1) & 3)) << 3);
            const __half* gA = g_xh + (size_t)(mBase + r) * K_DIM + kk + (cc << 3);
            unsigned dA = sptr(&sA[buf][sw]);
            asm volatile("cp.async.cg.shared.global [%0], [%1], 16;\n" :: "r"(dA), "l"(gA));
            const __half* gB = g_wh + (size_t)(nBase + r) * K_DIM + kk + (cc << 3);
            unsigned dB = sptr(&sB[buf][sw]);
            asm volatile("cp.async.cg.shared.global [%0], [%1], 16;\n" :: "r"(dB), "l"(gB));
        }
        asm volatile("cp.async.commit_group;\n");
    };

    load_tile(0, 0);

    for (int it = 0; it < NITER; it++) {
        int buf = it & 1;
        if (it + 1 < NITER) {
            load_tile(it + 1, buf ^ 1);
            asm volatile("cp.async.wait_group 1;\n");
        } else {
            asm volatile("cp.async.wait_group 0;\n");
        }
        __syncthreads();

#pragma unroll
        for (int ks = 0; ks < 2; ks++) {    // two k16 steps per BK=32
            unsigned af[4][4];
#pragma unroll
            for (int mi = 0; mi < 4; mi++) {
                int mat = lane >> 3;
                int r   = wm * 64 + mi * 16 + ((mat & 1) << 3) + (lane & 7);
                int cc  = ks * 2 + (mat >> 1);
                int sw  = r * BK + (((cc) ^ ((r >> 1) & 3)) << 3);
                unsigned addr = sptr(&sA[buf][sw]);
                asm volatile(
                    "ldmatrix.sync.aligned.m8n8.x4.shared.b16 {%0,%1,%2,%3}, [%4];\n"
                    : "=r"(af[mi][0]), "=r"(af[mi][1]), "=r"(af[mi][2]), "=r"(af[mi][3])
                    : "r"(addr));
            }
            unsigned bf[4][2];
#pragma unroll
            for (int p = 0; p < 2; p++) {
                int mat = lane >> 3;
                int r   = wn * 32 + p * 16 + ((mat >> 1) << 3) + (lane & 7);
                int cc  = ks * 2 + (mat & 1);
                int sw  = r * BK + (((cc) ^ ((r >> 1) & 3)) << 3);
                unsigned addr = sptr(&sB[buf][sw]);
                unsigned r0, r1, r2, r3;
                asm volatile(
                    "ldmatrix.sync.aligned.m8n8.x4.shared.b16 {%0,%1,%2,%3}, [%4];\n"
                    : "=r"(r0), "=r"(r1), "=r"(r2), "=r"(r3)
                    : "r"(addr));
                bf[p * 2][0]     = r0;
                bf[p * 2][1]     = r1;
                bf[p * 2 + 1][0] = r2;
                bf[p * 2 + 1][1] = r3;
            }
#pragma unroll
            for (int mi = 0; mi < 4; mi++)
#pragma unroll
                for (int ni = 0; ni < 4; ni++) {
                    asm volatile(
                        "mma.sync.aligned.m16n8k16.row.col.f32.f16.f16.f32 "
                        "{%0,%1,%2,%3}, {%4,%5,%6,%7}, {%8,%9}, {%0,%1,%2,%3};\n"
                        : "+f"(c[mi][ni][0]), "+f"(c[mi][ni][1]),
                          "+f"(c[mi][ni][2]), "+f"(c[mi][ni][3])
                        : "r"(af[mi][0]), "r"(af[mi][1]), "r"(af[mi][2]), "r"(af[mi][3]),
                          "r"(bf[ni][0]), "r"(bf[ni][1]));
                }
        }
        __syncthreads();
    }

    // Epilogue: bias add + fp32 store
#pragma unroll
    for (int mi = 0; mi < 4; mi++) {
        int row0 = mBase + wm * 64 + mi * 16 + (lane >> 2);
#pragma unroll
        for (int ni = 0; ni < 4; ni++) {
            int col = nBase + wn * 32 + ni * 8 + ((lane & 3) << 1);
            float b0 = __ldg(bias + col);
            float b1 = __ldg(bias + col + 1);
            out[(size_t)row0 * N_DIM + col]           = c[mi][ni][0] + b0;
            out[(size_t)row0 * N_DIM + col + 1]       = c[mi][ni][1] + b1;
            out[(size_t)(row0 + 8) * N_DIM + col]     = c[mi][ni][2] + b0;
            out[(size_t)(row0 + 8) * N_DIM + col + 1] = c[mi][ni][3] + b1;
        }
    }
}

// ---------------------------------------------------------------------------
extern "C" void kernel_launch(void* const* d_in, const int* in_sizes, int n_in,
                              void* d_out, int out_size)
{
    const float* x    = (const float*)d_in[0];
    const float* w    = (const float*)d_in[1];
    const float* bias = (const float*)d_in[2];
    float* out        = (float*)d_out;

    const int xquads = M_DIM * K_DIM / 16;
    const int wquads = N_DIM * K_DIM / 16;

    quant_kernel<<<(xquads * 4 + 255) / 256, 256>>>(x, 0, xquads);
    quant_kernel<<<(wquads * 4 + 255) / 256, 256>>>(w, 1, wquads);

    dim3 grid(N_DIM / BN, M_DIM / BM);
    gemm_kernel<<<grid, 256>>>(bias, out);
}

// round 5
// speedup vs baseline: 2.7433x; 1.0741x over previous
#include <cuda_runtime.h>
#include <cuda_fp16.h>
#include <cstdint>

#define M_DIM 8192
#define N_DIM 4096
#define K_DIM 4096

#define BM 128
#define BN 128
#define BK 64                   // K elements per stage (128 bytes/row)
#define STAGES 3
#define NITER (K_DIM / BK)      // 64
#define STAGE_HALVES (BM * BK + BN * BK)   // 16384 (32KB)
#define SMEM_BYTES (STAGES * STAGE_HALVES * 2)  // 96KB

// Scratch: fp16 quant-dequantized x and w.
__device__ __half g_xh[(size_t)M_DIM * K_DIM];
__device__ __half g_wh[(size_t)N_DIM * K_DIM];

// ---------------------------------------------------------------------------
// Quant kernel (proven): quad per 16-elem NVFP4 block.
// ---------------------------------------------------------------------------
__global__ void quant_kernel(const float* __restrict__ src, int is_w, int nquads)
{
    int t = blockIdx.x * blockDim.x + threadIdx.x;
    int quad = t >> 2;
    int lq = t & 3;
    if (quad >= nquads) return;

    __half* __restrict__ H = is_w ? g_wh : g_xh;

    size_t base = (size_t)quad * 16 + (size_t)lq * 4;
    float4 v = *reinterpret_cast<const float4*>(src + base);

    float amax = fmaxf(fmaxf(fabsf(v.x), fabsf(v.y)), fmaxf(fabsf(v.z), fabsf(v.w)));
    amax = fmaxf(amax, __shfl_xor_sync(0xffffffffu, amax, 1));
    amax = fmaxf(amax, __shfl_xor_sync(0xffffffffu, amax, 2));

    float scale = (amax > 0.0f) ? (amax / 6.0f) : 1.0f;

    float vals[4] = {v.x, v.y, v.z, v.w};
    unsigned short hs[4];
#pragma unroll
    for (int i = 0; i < 4; i++) {
        float y = vals[i] / scale;
        float a = fabsf(y);
        a = fminf(a, 6.0f);
        if (a <= 2.0f)       a = rintf(a * 2.0f) * 0.5f;
        else if (a <= 4.0f)  a = rintf(a);
        else                 a = rintf(a * 0.5f) * 2.0f;
        float q  = copysignf(a, y);
        float xq = q * scale;
        hs[i] = __half_as_ushort(__float2half_rn(xq));
    }
    uint2 hp;
    hp.x = (unsigned)hs[0] | ((unsigned)hs[1] << 16);
    hp.y = (unsigned)hs[2] | ((unsigned)hs[3] << 16);
    *reinterpret_cast<uint2*>(H + base) = hp;
}

// ---------------------------------------------------------------------------
// GEMM: C = Xq * Wq^T (+ bias). 128x128 CTA, BK=64, 3-stage cp.async pipe,
// ONE __syncthreads per iteration. 8 warps (2x4), warp tile 64x32.
// ---------------------------------------------------------------------------
__device__ __forceinline__ unsigned sptr(const void* p)
{
    return (unsigned)__cvta_generic_to_shared(p);
}

__global__ __launch_bounds__(256, 2)
void gemm_kernel(const float* __restrict__ bias, float* __restrict__ out)
{
    extern __shared__ __half smem[];   // STAGES * (A 8192 + B 8192) halves

    const int tid  = threadIdx.x;
    const int warp = tid >> 5;
    const int lane = tid & 31;
    const int wm = warp >> 2;   // 0..1
    const int wn = warp & 3;    // 0..3
    const int mBase = blockIdx.y * BM;
    const int nBase = blockIdx.x * BN;

    float c[4][4][4];
#pragma unroll
    for (int i = 0; i < 4; i++)
#pragma unroll
        for (int j = 0; j < 4; j++)
#pragma unroll
            for (int r = 0; r < 4; r++) c[i][j][r] = 0.0f;

    // 16B-chunk swizzle within a 128B row: chunk' = cc ^ (r & 7)
    auto load_tile = [&](int it, int buf) {
        int kk = it * BK;
        __half* sA = smem + buf * STAGE_HALVES;
        __half* sB = sA + BM * BK;
        const __half* Ab = g_xh + (size_t)mBase * K_DIM + kk;
        const __half* Bb = g_wh + (size_t)nBase * K_DIM + kk;
#pragma unroll
        for (int h = 0; h < 4; h++) {
            int q  = tid + h * 256;          // 0..1023
            int r  = q >> 3;                 // row 0..127
            int cc = q & 7;                  // 16B chunk 0..7
            int sw = r * BK + ((cc ^ (r & 7)) << 3);
            const __half* gA = Ab + (size_t)r * K_DIM + (cc << 3);
            asm volatile("cp.async.cg.shared.global [%0], [%1], 16;\n"
                         :: "r"(sptr(sA + sw)), "l"(gA));
            const __half* gB = Bb + (size_t)r * K_DIM + (cc << 3);
            asm volatile("cp.async.cg.shared.global [%0], [%1], 16;\n"
                         :: "r"(sptr(sB + sw)), "l"(gB));
        }
        asm volatile("cp.async.commit_group;\n");
    };

    // Prologue: stages 0 and 1
    load_tile(0, 0);
    load_tile(1, 1);

    int buf = 0;
    for (int it = 0; it < NITER; it++) {
        asm volatile("cp.async.wait_group 1;\n");   // stage `it` resident
        __syncthreads();                            // all done with stage it-1

        if (it + 2 < NITER) {
            int nb = buf + 2; if (nb >= STAGES) nb -= STAGES;  // == slot of it-1
            load_tile(it + 2, nb);
        }

        const __half* sA = smem + buf * STAGE_HALVES;
        const __half* sB = sA + BM * BK;

#pragma unroll
        for (int ks = 0; ks < 4; ks++) {    // four k16 steps per BK=64
            unsigned af[4][4];
#pragma unroll
            for (int mi = 0; mi < 4; mi++) {
                int mat = lane >> 3;
                int r   = wm * 64 + mi * 16 + ((mat & 1) << 3) + (lane & 7);
                int cc  = ks * 2 + (mat >> 1);
                int sw  = r * BK + ((cc ^ (r & 7)) << 3);
                asm volatile(
                    "ldmatrix.sync.aligned.m8n8.x4.shared.b16 {%0,%1,%2,%3}, [%4];\n"
                    : "=r"(af[mi][0]), "=r"(af[mi][1]), "=r"(af[mi][2]), "=r"(af[mi][3])
                    : "r"(sptr(sA + sw)));
            }
            unsigned bf[4][2];
#pragma unroll
            for (int p = 0; p < 2; p++) {
                int mat = lane >> 3;
                int r   = wn * 32 + p * 16 + ((mat >> 1) << 3) + (lane & 7);
                int cc  = ks * 2 + (mat & 1);
                int sw  = r * BK + ((cc ^ (r & 7)) << 3);
                unsigned r0, r1, r2, r3;
                asm volatile(
                    "ldmatrix.sync.aligned.m8n8.x4.shared.b16 {%0,%1,%2,%3}, [%4];\n"
                    : "=r"(r0), "=r"(r1), "=r"(r2), "=r"(r3)
                    : "r"(sptr(sB + sw)));
                bf[p * 2][0]     = r0;
                bf[p * 2][1]     = r1;
                bf[p * 2 + 1][0] = r2;
                bf[p * 2 + 1][1] = r3;
            }
#pragma unroll
            for (int mi = 0; mi < 4; mi++)
#pragma unroll
                for (int ni = 0; ni < 4; ni++) {
                    asm volatile(
                        "mma.sync.aligned.m16n8k16.row.col.f32.f16.f16.f32 "
                        "{%0,%1,%2,%3}, {%4,%5,%6,%7}, {%8,%9}, {%0,%1,%2,%3};\n"
                        : "+f"(c[mi][ni][0]), "+f"(c[mi][ni][1]),
                          "+f"(c[mi][ni][2]), "+f"(c[mi][ni][3])
                        : "r"(af[mi][0]), "r"(af[mi][1]), "r"(af[mi][2]), "r"(af[mi][3]),
                          "r"(bf[ni][0]), "r"(bf[ni][1]));
                }
        }

        if (++buf == STAGES) buf = 0;
    }

    // Epilogue: bias add + fp32 store
#pragma unroll
    for (int mi = 0; mi < 4; mi++) {
        int row0 = mBase + wm * 64 + mi * 16 + (lane >> 2);
#pragma unroll
        for (int ni = 0; ni < 4; ni++) {
            int col = nBase + wn * 32 + ni * 8 + ((lane & 3) << 1);
            float b0 = __ldg(bias + col);
            float b1 = __ldg(bias + col + 1);
            out[(size_t)row0 * N_DIM + col]           = c[mi][ni][0] + b0;
            out[(size_t)row0 * N_DIM + col + 1]       = c[mi][ni][1] + b1;
            out[(size_t)(row0 + 8) * N_DIM + col]     = c[mi][ni][2] + b0;
            out[(size_t)(row0 + 8) * N_DIM + col + 1] = c[mi][ni][3] + b1;
        }
    }
}

// ---------------------------------------------------------------------------
extern "C" void kernel_launch(void* const* d_in, const int* in_sizes, int n_in,
                              void* d_out, int out_size)
{
    const float* x    = (const float*)d_in[0];
    const float* w    = (const float*)d_in[1];
    const float* bias = (const float*)d_in[2];
    float* out        = (float*)d_out;

    const int xquads = M_DIM * K_DIM / 16;
    const int wquads = N_DIM * K_DIM / 16;

    quant_kernel<<<(xquads * 4 + 255) / 256, 256>>>(x, 0, xquads);
    quant_kernel<<<(wquads * 4 + 255) / 256, 256>>>(w, 1, wquads);

    cudaFuncSetAttribute(gemm_kernel,
                         cudaFuncAttributeMaxDynamicSharedMemorySize, SMEM_BYTES);
    dim3 grid(N_DIM / BN, M_DIM / BM);
    gemm_kernel<<<grid, 256, SMEM_BYTES>>>(bias, out);
}